// round 1
// baseline (speedup 1.0000x reference)
#include <cuda_runtime.h>
#include <cstddef>

// LocalAttention: B=4, S=2048, D=256, W=33
// out = [values (B,S,D) | p_attn (B,S,W)] as float32

#define S_LEN   2048
#define D_DIM   256
#define B_SZ    4
#define W_SZ    33
#define HALF_W  16
#define TILE_Q  64                 // queries per CTA
#define THREADS 512                // 16 warps
#define QW      4                  // queries per warp
#define ROWS    (TILE_Q + 2*HALF_W)  // 96 K/V rows staged in smem
#define D4      (D_DIM/4)          // 64 float4 per row

// smem layout (bytes):
//   K tile : ROWS*D_DIM*4      = 98304
//   V tile : ROWS*D_DIM*4      = 98304
//   scores : TILE_Q*W_SZ*4     =  8448
//   flags  : ROWS*4            =   384
// total = 205440
#define SMEM_BYTES (ROWS*D_DIM*4*2 + TILE_Q*W_SZ*4 + ROWS*4)

__global__ void __launch_bounds__(THREADS, 1)
local_attn_kernel(const float* __restrict__ qg,
                  const float* __restrict__ kg,
                  const float* __restrict__ vg,
                  const int*   __restrict__ maskg,
                  float* __restrict__ out_vals,
                  float* __restrict__ out_p)
{
    extern __shared__ float smem[];
    float4* Ksm = reinterpret_cast<float4*>(smem);
    float4* Vsm = Ksm + ROWS * D4;
    float*  Ssm = reinterpret_cast<float*>(Vsm + ROWS * D4);   // [TILE_Q][W_SZ]
    int*    Fsm = reinterpret_cast<int*>(Ssm + TILE_Q * W_SZ); // [ROWS]

    const int tile = blockIdx.x;           // 0..31
    const int b    = blockIdx.y;           // 0..3
    const int base = tile * TILE_Q;        // first query of tile
    const int r0   = base - HALF_W;        // first (possibly <0) K/V row
    const int tid  = threadIdx.x;

    // ---- stage K/V tile (rows clamped to [0,S)) + mask flags ----
    const float4* kg4 = reinterpret_cast<const float4*>(kg + (size_t)b * S_LEN * D_DIM);
    const float4* vg4 = reinterpret_cast<const float4*>(vg + (size_t)b * S_LEN * D_DIM);
    #pragma unroll
    for (int it = 0; it < ROWS * D4 / THREADS; ++it) {   // 12 iters
        int idx  = tid + it * THREADS;
        int row  = idx >> 6;        // / D4
        int col  = idx & (D4 - 1);
        int grow = r0 + row;
        int gcl  = grow < 0 ? 0 : (grow >= S_LEN ? S_LEN - 1 : grow);
        Ksm[idx] = kg4[(size_t)gcl * D4 + col];
        Vsm[idx] = vg4[(size_t)gcl * D4 + col];
    }
    if (tid < ROWS) {
        int grow = r0 + tid;
        int f = 0;
        if (grow >= 0 && grow < S_LEN) f = (maskg[b * S_LEN + grow] != 0);
        Fsm[tid] = f;
    }
    __syncthreads();

    const int warp = tid >> 5;        // 0..15
    const int lane = tid & 31;
    const int g    = lane >> 3;       // query-group within warp, 0..3
    const int j    = lane & 7;        // d-lane within group
    const int lq0  = warp * QW;       // warp's first local query
    const int lq   = lq0 + g;         // this group's local query
    const int gq   = base + lq;       // global query row

    // ---- load query fragment: lane j holds float4s at byte offset j*16 + i*128 ----
    float4 qf[8];
    const float4* qrow = reinterpret_cast<const float4*>(qg + ((size_t)b * S_LEN + gq) * D_DIM);
    #pragma unroll
    for (int i = 0; i < 8; ++i) qf[i] = qrow[i * 8 + j];

    // ---- pass 1: scores ----
    #pragma unroll 2
    for (int r = 0; r < QW + 2 * HALF_W; ++r) {   // 36 rows per warp
        int m = lq0 + r;                          // smem row index
        float partial = 0.f;
        #pragma unroll
        for (int i = 0; i < 8; ++i) {
            float4 kk = Ksm[m * D4 + i * 8 + j];
            partial += kk.x * qf[i].x + kk.y * qf[i].y
                     + kk.z * qf[i].z + kk.w * qf[i].w;
        }
        // reduce across the 8 lanes of this group (all 4 groups at once)
        partial += __shfl_xor_sync(0xffffffffu, partial, 4);
        partial += __shfl_xor_sync(0xffffffffu, partial, 2);
        partial += __shfl_xor_sync(0xffffffffu, partial, 1);
        int wpos = r - g;                         // window position for this group's query
        if (j == 0 && wpos >= 0 && wpos < W_SZ) {
            float sc = Fsm[m] ? partial * 0.0625f : -1e10f;   // /sqrt(256)
            Ssm[lq * W_SZ + wpos] = sc;
        }
    }
    __syncthreads();

    // ---- softmax: one thread per query ----
    if (tid < TILE_Q) {
        float* row = Ssm + tid * W_SZ;
        float mx = row[0];
        #pragma unroll
        for (int w = 1; w < W_SZ; ++w) mx = fmaxf(mx, row[w]);
        float sum = 0.f;
        #pragma unroll
        for (int w = 0; w < W_SZ; ++w) {
            float e = __expf(row[w] - mx);
            sum += e;
            row[w] = e;
        }
        float inv = 1.f / sum;
        float* po = out_p + ((size_t)b * S_LEN + base + tid) * W_SZ;
        #pragma unroll
        for (int w = 0; w < W_SZ; ++w) {
            float p = row[w] * inv;
            row[w] = p;
            po[w] = p;
        }
    }
    __syncthreads();

    // ---- pass 2: values = sum_w p * V ----
    float4 acc[8];
    #pragma unroll
    for (int i = 0; i < 8; ++i) acc[i] = make_float4(0.f, 0.f, 0.f, 0.f);

    #pragma unroll 2
    for (int r = 0; r < QW + 2 * HALF_W; ++r) {   // 36
        int m = lq0 + r;
        int wpos = r - g;
        float p = (wpos >= 0 && wpos < W_SZ) ? Ssm[lq * W_SZ + wpos] : 0.f;
        #pragma unroll
        for (int i = 0; i < 8; ++i) {
            float4 vv = Vsm[m * D4 + i * 8 + j];
            acc[i].x += p * vv.x;
            acc[i].y += p * vv.y;
            acc[i].z += p * vv.z;
            acc[i].w += p * vv.w;
        }
    }

    float4* orow = reinterpret_cast<float4*>(out_vals + ((size_t)b * S_LEN + gq) * D_DIM);
    #pragma unroll
    for (int i = 0; i < 8; ++i) orow[i * 8 + j] = acc[i];
}

extern "C" void kernel_launch(void* const* d_in, const int* in_sizes, int n_in,
                              void* d_out, int out_size)
{
    const float* q    = (const float*)d_in[0];
    const float* k    = (const float*)d_in[1];
    const float* v    = (const float*)d_in[2];
    const int*   mask = (const int*)d_in[3];

    float* out_vals = (float*)d_out;
    float* out_p    = out_vals + (size_t)B_SZ * S_LEN * D_DIM;

    static bool attr_set = false;
    if (!attr_set) {
        cudaFuncSetAttribute(local_attn_kernel,
                             cudaFuncAttributeMaxDynamicSharedMemorySize,
                             SMEM_BYTES);
        attr_set = true;
    }

    dim3 grid(S_LEN / TILE_Q, B_SZ);   // (32, 4) = 128 CTAs, one wave
    local_attn_kernel<<<grid, THREADS, SMEM_BYTES>>>(q, k, v, mask, out_vals, out_p);
}

// round 2
// speedup vs baseline: 1.0955x; 1.0955x over previous
#include <cuda_runtime.h>
#include <cstddef>

// LocalAttention: B=4, S=2048, D=256, W=33
// out = [values (B,S,D) | p_attn (B,S,W)] as float32

#define S_LEN   2048
#define D_DIM   256
#define B_SZ    4
#define W_SZ    33
#define HALF_W  16
#define TILE_Q  64                 // queries per CTA
#define THREADS 512                // 16 warps
#define QW      4                  // queries per warp
#define ROWS    (TILE_Q + 2*HALF_W)  // 96 K/V rows staged in smem
#define D4      (D_DIM/4)          // 64 float4 per row

// smem layout (bytes):
//   K tile : ROWS*D_DIM*4      = 98304
//   V tile : ROWS*D_DIM*4      = 98304
//   scores : TILE_Q*W_SZ*4     =  8448
//   flags  : ROWS*4            =   384
#define SMEM_BYTES (ROWS*D_DIM*4*2 + TILE_Q*W_SZ*4 + ROWS*4)

__global__ void __launch_bounds__(THREADS, 1)
local_attn_kernel(const float* __restrict__ qg,
                  const float* __restrict__ kg,
                  const float* __restrict__ vg,
                  const int*   __restrict__ maskg,
                  float* __restrict__ out_vals,
                  float* __restrict__ out_p)
{
    extern __shared__ float smem[];
    float4* Ksm = reinterpret_cast<float4*>(smem);
    float4* Vsm = Ksm + ROWS * D4;
    float*  Ssm = reinterpret_cast<float*>(Vsm + ROWS * D4);   // [TILE_Q][W_SZ]
    int*    Fsm = reinterpret_cast<int*>(Ssm + TILE_Q * W_SZ); // [ROWS]

    const int tile = blockIdx.x;           // 0..31
    const int b    = blockIdx.y;           // 0..3
    const int base = tile * TILE_Q;        // first query of tile
    const int r0   = base - HALF_W;        // first (possibly <0) K/V row
    const int tid  = threadIdx.x;

    // ---- stage K/V tile (rows clamped to [0,S)) + mask flags ----
    const float4* kg4 = reinterpret_cast<const float4*>(kg + (size_t)b * S_LEN * D_DIM);
    const float4* vg4 = reinterpret_cast<const float4*>(vg + (size_t)b * S_LEN * D_DIM);
    #pragma unroll
    for (int it = 0; it < ROWS * D4 / THREADS; ++it) {   // 12 iters
        int idx  = tid + it * THREADS;
        int row  = idx >> 6;        // / D4
        int col  = idx & (D4 - 1);
        int grow = r0 + row;
        int gcl  = grow < 0 ? 0 : (grow >= S_LEN ? S_LEN - 1 : grow);
        Ksm[idx] = kg4[(size_t)gcl * D4 + col];
        Vsm[idx] = vg4[(size_t)gcl * D4 + col];
    }
    if (tid < ROWS) {
        int grow = r0 + tid;
        int f = 0;
        if (grow >= 0 && grow < S_LEN) f = (maskg[b * S_LEN + grow] != 0);
        Fsm[tid] = f;
    }
    __syncthreads();   // the ONLY block-wide barrier

    const int warp = tid >> 5;        // 0..15
    const int lane = tid & 31;
    const int g    = lane >> 3;       // query-group within warp, 0..3
    const int j    = lane & 7;        // d-lane within group
    const int lq0  = warp * QW;       // warp's first local query
    const int lq   = lq0 + g;         // this group's local query
    const int gq   = base + lq;       // global query row

    // ---- load query fragment: lane j holds float4s at offset j*16B + i*128B ----
    float4 qf[8];
    const float4* qrow = reinterpret_cast<const float4*>(qg + ((size_t)b * S_LEN + gq) * D_DIM);
    #pragma unroll
    for (int i = 0; i < 8; ++i) qf[i] = qrow[i * 8 + j];

    float* srow = Ssm + lq * W_SZ;    // this group's score row

    // ---- pass 1: scores (4 parallel accumulator chains, depth 8) ----
    #pragma unroll 4
    for (int r = 0; r < QW + 2 * HALF_W; ++r) {   // 36 rows per warp
        int m = lq0 + r;                          // smem row index
        float ax = 0.f, ay = 0.f, az = 0.f, aw = 0.f;
        #pragma unroll
        for (int i = 0; i < 8; ++i) {
            float4 kk = Ksm[m * D4 + i * 8 + j];
            ax = fmaf(kk.x, qf[i].x, ax);
            ay = fmaf(kk.y, qf[i].y, ay);
            az = fmaf(kk.z, qf[i].z, az);
            aw = fmaf(kk.w, qf[i].w, aw);
        }
        float partial = (ax + ay) + (az + aw);
        // reduce across the 8 lanes of this group (all 4 groups at once)
        partial += __shfl_xor_sync(0xffffffffu, partial, 4);
        partial += __shfl_xor_sync(0xffffffffu, partial, 2);
        partial += __shfl_xor_sync(0xffffffffu, partial, 1);
        int wpos = r - g;                         // window position for this group's query
        if (j == 0 && wpos >= 0 && wpos < W_SZ) {
            float sc = Fsm[m] ? partial * 0.0625f : -1e10f;   // /sqrt(256)
            srow[wpos] = sc;
        }
    }
    __syncwarp();   // scores for this warp's queries written only by this warp

    // ---- warp-local softmax: 8 lanes per query, all queries in parallel ----
    {
        float s0 = srow[j];
        float s1 = srow[j + 8];
        float s2 = srow[j + 16];
        float s3 = srow[j + 24];
        float s4 = (j == 0) ? srow[32] : -3e38f;

        float mx = fmaxf(fmaxf(fmaxf(s0, s1), fmaxf(s2, s3)), s4);
        mx = fmaxf(mx, __shfl_xor_sync(0xffffffffu, mx, 4));
        mx = fmaxf(mx, __shfl_xor_sync(0xffffffffu, mx, 2));
        mx = fmaxf(mx, __shfl_xor_sync(0xffffffffu, mx, 1));

        float e0 = __expf(s0 - mx);
        float e1 = __expf(s1 - mx);
        float e2 = __expf(s2 - mx);
        float e3 = __expf(s3 - mx);
        float e4 = (j == 0) ? __expf(s4 - mx) : 0.f;

        float sum = ((e0 + e1) + (e2 + e3)) + e4;
        sum += __shfl_xor_sync(0xffffffffu, sum, 4);
        sum += __shfl_xor_sync(0xffffffffu, sum, 2);
        sum += __shfl_xor_sync(0xffffffffu, sum, 1);
        float inv = 1.f / sum;

        float p0 = e0 * inv, p1 = e1 * inv, p2 = e2 * inv, p3 = e3 * inv;
        srow[j]      = p0;
        srow[j + 8]  = p1;
        srow[j + 16] = p2;
        srow[j + 24] = p3;

        float* po = out_p + (size_t)(b * S_LEN + gq) * W_SZ;
        po[j]      = p0;
        po[j + 8]  = p1;
        po[j + 16] = p2;
        po[j + 24] = p3;
        if (j == 0) {
            float p4 = e4 * inv;
            srow[32] = p4;
            po[32]   = p4;
        }
    }
    __syncwarp();

    // ---- pass 2: values = sum_w p * V (32 independent accumulator chains) ----
    float4 acc[8];
    #pragma unroll
    for (int i = 0; i < 8; ++i) acc[i] = make_float4(0.f, 0.f, 0.f, 0.f);

    #pragma unroll 4
    for (int r = 0; r < QW + 2 * HALF_W; ++r) {   // 36
        int m = lq0 + r;
        int wpos = r - g;
        float p = (wpos >= 0 && wpos < W_SZ) ? srow[wpos] : 0.f;
        #pragma unroll
        for (int i = 0; i < 8; ++i) {
            float4 vv = Vsm[m * D4 + i * 8 + j];
            acc[i].x = fmaf(p, vv.x, acc[i].x);
            acc[i].y = fmaf(p, vv.y, acc[i].y);
            acc[i].z = fmaf(p, vv.z, acc[i].z);
            acc[i].w = fmaf(p, vv.w, acc[i].w);
        }
    }

    float4* orow = reinterpret_cast<float4*>(out_vals + ((size_t)b * S_LEN + gq) * D_DIM);
    #pragma unroll
    for (int i = 0; i < 8; ++i) orow[i * 8 + j] = acc[i];
}

extern "C" void kernel_launch(void* const* d_in, const int* in_sizes, int n_in,
                              void* d_out, int out_size)
{
    const float* q    = (const float*)d_in[0];
    const float* k    = (const float*)d_in[1];
    const float* v    = (const float*)d_in[2];
    const int*   mask = (const int*)d_in[3];

    float* out_vals = (float*)d_out;
    float* out_p    = out_vals + (size_t)B_SZ * S_LEN * D_DIM;

    static bool attr_set = false;
    if (!attr_set) {
        cudaFuncSetAttribute(local_attn_kernel,
                             cudaFuncAttributeMaxDynamicSharedMemorySize,
                             SMEM_BYTES);
        attr_set = true;
    }

    dim3 grid(S_LEN / TILE_Q, B_SZ);   // (32, 4) = 128 CTAs, one wave
    local_attn_kernel<<<grid, THREADS, SMEM_BYTES>>>(q, k, v, mask, out_vals, out_p);
}

// round 3
// speedup vs baseline: 1.2650x; 1.1547x over previous
#include <cuda_runtime.h>
#include <cstddef>

// LocalAttention: B=4, S=2048, D=256, W=33
// out = [values (B,S,D) | p_attn (B,S,W)] as float32

#define S_LEN   2048
#define D_DIM   256
#define B_SZ    4
#define W_SZ    33
#define HALF_W  16
#define TILE_Q  64                 // queries per CTA
#define THREADS 512                // 16 warps
#define QW      4                  // queries per warp
#define ROWS    (TILE_Q + 2*HALF_W)  // 96 K/V rows staged in smem
#define D4      (D_DIM/4)          // 64 float4 per row
#define NR      (QW + 2*HALF_W)    // 36 rows per warp

// smem: K + V tiles, scores, mask flags
#define SMEM_BYTES (ROWS*D_DIM*4*2 + TILE_Q*W_SZ*4 + ROWS*4)

__global__ void __launch_bounds__(THREADS, 1)
local_attn_kernel(const float* __restrict__ qg,
                  const float* __restrict__ kg,
                  const float* __restrict__ vg,
                  const int*   __restrict__ maskg,
                  float* __restrict__ out_vals,
                  float* __restrict__ out_p)
{
    extern __shared__ float smem[];
    float4* Ksm = reinterpret_cast<float4*>(smem);
    float4* Vsm = Ksm + ROWS * D4;
    float*  Ssm = reinterpret_cast<float*>(Vsm + ROWS * D4);   // [TILE_Q][W_SZ]
    int*    Fsm = reinterpret_cast<int*>(Ssm + TILE_Q * W_SZ); // [ROWS]

    const int tile = blockIdx.x;
    const int b    = blockIdx.y;
    const int base = tile * TILE_Q;
    const int r0   = base - HALF_W;
    const int tid  = threadIdx.x;

    // ---- stage K/V tile (rows clamped to [0,S)) + mask flags ----
    const float4* kg4 = reinterpret_cast<const float4*>(kg + (size_t)b * S_LEN * D_DIM);
    const float4* vg4 = reinterpret_cast<const float4*>(vg + (size_t)b * S_LEN * D_DIM);
    #pragma unroll
    for (int it = 0; it < ROWS * D4 / THREADS; ++it) {   // 12 iters
        int idx  = tid + it * THREADS;
        int row  = idx >> 6;
        int col  = idx & (D4 - 1);
        int grow = r0 + row;
        int gcl  = grow < 0 ? 0 : (grow >= S_LEN ? S_LEN - 1 : grow);
        Ksm[idx] = kg4[(size_t)gcl * D4 + col];
        Vsm[idx] = vg4[(size_t)gcl * D4 + col];
    }
    if (tid < ROWS) {
        int grow = r0 + tid;
        int f = 0;
        if (grow >= 0 && grow < S_LEN) f = (maskg[b * S_LEN + grow] != 0);
        Fsm[tid] = f;
    }
    __syncthreads();   // only block-wide barrier

    const int warp = tid >> 5;        // 0..15
    const int lane = tid & 31;
    const int g    = lane >> 3;       // 8-lane group id (used for reduction/softmax)
    const int j    = lane & 7;
    const int lq0  = warp * QW;       // warp's first local query
    const int lq   = lq0 + g;
    const int gq   = base + lq;

    // ---- Q fragments: lane holds floats [8*lane, 8*lane+8) of ALL 4 queries ----
    float4 qa[QW], qb[QW];
    const float4* qbase = reinterpret_cast<const float4*>(
        qg + ((size_t)b * S_LEN + base + lq0) * D_DIM);
    #pragma unroll
    for (int q = 0; q < QW; ++q) {
        qa[q] = qbase[q * D4 + 2 * lane];
        qb[q] = qbase[q * D4 + 2 * lane + 1];
    }

    float* srow = Ssm + lq * W_SZ;

    // ---- pass 1: scores. Per row: 2 unique LDS.128/lane, 32 FMA, 11 shfl ----
    #pragma unroll 4
    for (int r = 0; r < NR; ++r) {
        int m = lq0 + r;
        const float4* krow = Ksm + m * D4 + 2 * lane;
        float4 k0 = krow[0];
        float4 k1 = krow[1];

        float s0, s1, s2, s3;
        {
            s0 = k0.x*qa[0].x + k0.y*qa[0].y + k0.z*qa[0].z + k0.w*qa[0].w
               + k1.x*qb[0].x + k1.y*qb[0].y + k1.z*qb[0].z + k1.w*qb[0].w;
            s1 = k0.x*qa[1].x + k0.y*qa[1].y + k0.z*qa[1].z + k0.w*qa[1].w
               + k1.x*qb[1].x + k1.y*qb[1].y + k1.z*qb[1].z + k1.w*qb[1].w;
            s2 = k0.x*qa[2].x + k0.y*qa[2].y + k0.z*qa[2].z + k0.w*qa[2].w
               + k1.x*qb[2].x + k1.y*qb[2].y + k1.z*qb[2].z + k1.w*qb[2].w;
            s3 = k0.x*qa[3].x + k0.y*qa[3].y + k0.z*qa[3].z + k0.w*qa[3].w
               + k1.x*qb[3].x + k1.y*qb[3].y + k1.z*qb[3].z + k1.w*qb[3].w;
        }
        // reduce all 4 partials over lanes {l, l^8, l^16, l^24}
        s0 += __shfl_xor_sync(0xffffffffu, s0, 16);
        s1 += __shfl_xor_sync(0xffffffffu, s1, 16);
        s2 += __shfl_xor_sync(0xffffffffu, s2, 16);
        s3 += __shfl_xor_sync(0xffffffffu, s3, 16);
        s0 += __shfl_xor_sync(0xffffffffu, s0, 8);
        s1 += __shfl_xor_sync(0xffffffffu, s1, 8);
        s2 += __shfl_xor_sync(0xffffffffu, s2, 8);
        s3 += __shfl_xor_sync(0xffffffffu, s3, 8);
        // group g finishes query g: reduce over its 8 lanes
        float v = (g == 0) ? s0 : (g == 1) ? s1 : (g == 2) ? s2 : s3;
        v += __shfl_xor_sync(0xffffffffu, v, 4);
        v += __shfl_xor_sync(0xffffffffu, v, 2);
        v += __shfl_xor_sync(0xffffffffu, v, 1);

        int wpos = r - g;
        if (j == 0 && wpos >= 0 && wpos < W_SZ) {
            float sc = Fsm[m] ? v * 0.0625f : -1e10f;   // * 1/sqrt(256)
            srow[wpos] = sc;
        }
    }
    __syncwarp();

    // ---- warp-local softmax: 8 lanes per query (group g handles query lq0+g) ----
    {
        float s0 = srow[j];
        float s1 = srow[j + 8];
        float s2 = srow[j + 16];
        float s3 = srow[j + 24];
        float s4 = (j == 0) ? srow[32] : -3e38f;

        float mx = fmaxf(fmaxf(fmaxf(s0, s1), fmaxf(s2, s3)), s4);
        mx = fmaxf(mx, __shfl_xor_sync(0xffffffffu, mx, 4));
        mx = fmaxf(mx, __shfl_xor_sync(0xffffffffu, mx, 2));
        mx = fmaxf(mx, __shfl_xor_sync(0xffffffffu, mx, 1));

        float e0 = __expf(s0 - mx);
        float e1 = __expf(s1 - mx);
        float e2 = __expf(s2 - mx);
        float e3 = __expf(s3 - mx);
        float e4 = (j == 0) ? __expf(s4 - mx) : 0.f;

        float sum = ((e0 + e1) + (e2 + e3)) + e4;
        sum += __shfl_xor_sync(0xffffffffu, sum, 4);
        sum += __shfl_xor_sync(0xffffffffu, sum, 2);
        sum += __shfl_xor_sync(0xffffffffu, sum, 1);
        float inv = 1.f / sum;

        float p0 = e0 * inv, p1 = e1 * inv, p2 = e2 * inv, p3 = e3 * inv;
        srow[j]      = p0;
        srow[j + 8]  = p1;
        srow[j + 16] = p2;
        srow[j + 24] = p3;

        float* po = out_p + (size_t)(b * S_LEN + gq) * W_SZ;
        po[j]      = p0;
        po[j + 8]  = p1;
        po[j + 16] = p2;
        po[j + 24] = p3;
        if (j == 0) {
            float p4 = e4 * inv;
            srow[32] = p4;
            po[32]   = p4;
        }
    }
    __syncwarp();

    // ---- pass 2: lane accumulates d-slice [8l,8l+8) of all 4 queries ----
    float4 aa[QW], ab[QW];
    #pragma unroll
    for (int q = 0; q < QW; ++q) {
        aa[q] = make_float4(0.f, 0.f, 0.f, 0.f);
        ab[q] = make_float4(0.f, 0.f, 0.f, 0.f);
    }

    const float* sbase = Ssm + lq0 * W_SZ;
    #pragma unroll 4
    for (int r = 0; r < NR; ++r) {
        int m = lq0 + r;
        const float4* vrow = Vsm + m * D4 + 2 * lane;
        float4 v0 = vrow[0];
        float4 v1 = vrow[1];
        #pragma unroll
        for (int q = 0; q < QW; ++q) {
            int wpos = r - q;
            float p = (wpos >= 0 && wpos < W_SZ) ? sbase[q * W_SZ + wpos] : 0.f;
            aa[q].x = fmaf(p, v0.x, aa[q].x);
            aa[q].y = fmaf(p, v0.y, aa[q].y);
            aa[q].z = fmaf(p, v0.z, aa[q].z);
            aa[q].w = fmaf(p, v0.w, aa[q].w);
            ab[q].x = fmaf(p, v1.x, ab[q].x);
            ab[q].y = fmaf(p, v1.y, ab[q].y);
            ab[q].z = fmaf(p, v1.z, ab[q].z);
            ab[q].w = fmaf(p, v1.w, ab[q].w);
        }
    }

    float4* obase = reinterpret_cast<float4*>(
        out_vals + ((size_t)b * S_LEN + base + lq0) * D_DIM);
    #pragma unroll
    for (int q = 0; q < QW; ++q) {
        obase[q * D4 + 2 * lane]     = aa[q];
        obase[q * D4 + 2 * lane + 1] = ab[q];
    }
}

extern "C" void kernel_launch(void* const* d_in, const int* in_sizes, int n_in,
                              void* d_out, int out_size)
{
    const float* q    = (const float*)d_in[0];
    const float* k    = (const float*)d_in[1];
    const float* v    = (const float*)d_in[2];
    const int*   mask = (const int*)d_in[3];

    float* out_vals = (float*)d_out;
    float* out_p    = out_vals + (size_t)B_SZ * S_LEN * D_DIM;

    static bool attr_set = false;
    if (!attr_set) {
        cudaFuncSetAttribute(local_attn_kernel,
                             cudaFuncAttributeMaxDynamicSharedMemorySize,
                             SMEM_BYTES);
        attr_set = true;
    }

    dim3 grid(S_LEN / TILE_Q, B_SZ);   // 128 CTAs, one wave
    local_attn_kernel<<<grid, THREADS, SMEM_BYTES>>>(q, k, v, mask, out_vals, out_p);
}

// round 4
// speedup vs baseline: 1.5158x; 1.1983x over previous
#include <cuda_runtime.h>
#include <cstddef>
#include <cstdint>

// LocalAttention: B=4, S=2048, D=256, W=33
// out = [values (B,S,D) | p_attn (B,S,W)] as float32

#define S_LEN   2048
#define D_DIM   256
#define B_SZ    4
#define W_SZ    33
#define HALF_W  16
#define TILE_Q  64
#define THREADS 512                // 16 warps
#define QW      4                  // queries per warp
#define ROWS    (TILE_Q + 2*HALF_W)  // 96 K/V rows in smem
#define D4      (D_DIM/4)          // 64 float4 per row
#define NR      (QW + 2*HALF_W)    // 36 rows per warp

#define SMEM_BYTES (ROWS*D_DIM*4*2 + TILE_Q*W_SZ*4 + ROWS*4)

typedef unsigned long long ull;

__device__ __forceinline__ ull fma2(ull a, ull b, ull c) {
    ull d;
    asm("fma.rn.f32x2 %0, %1, %2, %3;" : "=l"(d) : "l"(a), "l"(b), "l"(c));
    return d;
}
__device__ __forceinline__ float f32x2_sum(ull v) {
    float lo, hi;
    asm("mov.b64 {%0, %1}, %2;" : "=f"(lo), "=f"(hi) : "l"(v));
    return lo + hi;
}
__device__ __forceinline__ ull pack2(float x) {
    ull d;
    asm("mov.b64 %0, {%1, %1};" : "=l"(d) : "f"(x));
    return d;
}

__global__ void __launch_bounds__(THREADS, 1)
local_attn_kernel(const float* __restrict__ qg,
                  const float* __restrict__ kg,
                  const float* __restrict__ vg,
                  const int*   __restrict__ maskg,
                  float* __restrict__ out_vals,
                  float* __restrict__ out_p)
{
    extern __shared__ float smem[];
    float4* Ksm = reinterpret_cast<float4*>(smem);
    float4* Vsm = Ksm + ROWS * D4;
    float*  Ssm = reinterpret_cast<float*>(Vsm + ROWS * D4);   // [TILE_Q][W_SZ]
    int*    Fsm = reinterpret_cast<int*>(Ssm + TILE_Q * W_SZ); // [ROWS]

    const int tile = blockIdx.x;
    const int b    = blockIdx.y;
    const int base = tile * TILE_Q;
    const int r0   = base - HALF_W;
    const int tid  = threadIdx.x;

    // ---- stage K/V tile (rows clamped to [0,S)) + mask flags ----
    const float4* kg4 = reinterpret_cast<const float4*>(kg + (size_t)b * S_LEN * D_DIM);
    const float4* vg4 = reinterpret_cast<const float4*>(vg + (size_t)b * S_LEN * D_DIM);
    #pragma unroll
    for (int it = 0; it < ROWS * D4 / THREADS; ++it) {   // 12 iters
        int idx  = tid + it * THREADS;
        int row  = idx >> 6;
        int col  = idx & (D4 - 1);
        int grow = r0 + row;
        int gcl  = grow < 0 ? 0 : (grow >= S_LEN ? S_LEN - 1 : grow);
        Ksm[idx] = kg4[(size_t)gcl * D4 + col];
        Vsm[idx] = vg4[(size_t)gcl * D4 + col];
    }
    if (tid < ROWS) {
        int grow = r0 + tid;
        int f = 0;
        if (grow >= 0 && grow < S_LEN) f = (maskg[b * S_LEN + grow] != 0);
        Fsm[tid] = f;
    }
    __syncthreads();   // only block-wide barrier

    const int warp = tid >> 5;
    const int lane = tid & 31;
    const int lq0  = warp * QW;

    // pass-1 lane decomposition: h = row-half, p = 16-lane d-position
    const int h  = lane >> 4;        // 0/1 : which row of the pair
    const int p  = lane & 15;        // d-chunk position
    const int g4 = (lane >> 2) & 3;  // 4-lane group -> query for final reduce
    const bool wlane = ((lane & 3) == 0);

    // ---- Q fragments as packed f32x2 pairs: lane holds chunks p,p+16,p+32,p+48
    //      of all 4 queries (identical in both halves) ----
    ulonglong2 qf[QW][4];
    {
        const ulonglong2* qb = reinterpret_cast<const ulonglong2*>(
            qg + ((size_t)b * S_LEN + base + lq0) * D_DIM);
        #pragma unroll
        for (int q = 0; q < QW; ++q)
            #pragma unroll
            for (int c = 0; c < 4; ++c)
                qf[q][c] = qb[q * D4 + p + 16 * c];
    }

    const ulonglong2* Ksm2 = reinterpret_cast<const ulonglong2*>(Ksm);
    float* swarp = Ssm + lq0 * W_SZ;

    // ---- pass 1: scores, two rows per iteration ----
    #pragma unroll 2
    for (int ri = 0; ri < NR / 2; ++ri) {   // 18 iters
        int m = lq0 + 2 * ri + h;           // this half's smem row
        const ulonglong2* krow = Ksm2 + m * D4 + p;
        ulonglong2 k0 = krow[0];
        ulonglong2 k1 = krow[16];
        ulonglong2 k2 = krow[32];
        ulonglong2 k3 = krow[48];

        float s[QW];
        #pragma unroll
        for (int q = 0; q < QW; ++q) {
            ull a0 = fma2(k0.x, qf[q][0].x, 0ull);
            ull a1 = fma2(k0.y, qf[q][0].y, 0ull);
            a0 = fma2(k1.x, qf[q][1].x, a0);
            a1 = fma2(k1.y, qf[q][1].y, a1);
            a0 = fma2(k2.x, qf[q][2].x, a0);
            a1 = fma2(k2.y, qf[q][2].y, a1);
            a0 = fma2(k3.x, qf[q][3].x, a0);
            a1 = fma2(k3.y, qf[q][3].y, a1);
            s[q] = f32x2_sum(a0) + f32x2_sum(a1);
        }
        // reduce over the 16 d-lanes of this half (all 4 queries)
        #pragma unroll
        for (int q = 0; q < QW; ++q) s[q] += __shfl_xor_sync(0xffffffffu, s[q], 8);
        #pragma unroll
        for (int q = 0; q < QW; ++q) s[q] += __shfl_xor_sync(0xffffffffu, s[q], 4);
        // 4-lane group g4 finishes query g4
        float v = (g4 == 0) ? s[0] : (g4 == 1) ? s[1] : (g4 == 2) ? s[2] : s[3];
        v += __shfl_xor_sync(0xffffffffu, v, 2);
        v += __shfl_xor_sync(0xffffffffu, v, 1);

        int rl = 2 * ri + h;
        int wpos = rl - g4;
        if (wlane && wpos >= 0 && wpos < W_SZ) {
            float sc = Fsm[m] ? v * 0.0625f : -1e10f;   // * 1/sqrt(256)
            swarp[g4 * W_SZ + wpos] = sc;
        }
    }
    __syncwarp();

    // ---- warp-local softmax: 8 lanes per query ----
    const int g8 = lane >> 3;
    const int j  = lane & 7;
    const int lq = lq0 + g8;
    const int gq = base + lq;
    float* srow = Ssm + lq * W_SZ;
    {
        float s0 = srow[j];
        float s1 = srow[j + 8];
        float s2 = srow[j + 16];
        float s3 = srow[j + 24];
        float s4 = (j == 0) ? srow[32] : -3e38f;

        float mx = fmaxf(fmaxf(fmaxf(s0, s1), fmaxf(s2, s3)), s4);
        mx = fmaxf(mx, __shfl_xor_sync(0xffffffffu, mx, 4));
        mx = fmaxf(mx, __shfl_xor_sync(0xffffffffu, mx, 2));
        mx = fmaxf(mx, __shfl_xor_sync(0xffffffffu, mx, 1));

        float e0 = __expf(s0 - mx);
        float e1 = __expf(s1 - mx);
        float e2 = __expf(s2 - mx);
        float e3 = __expf(s3 - mx);
        float e4 = (j == 0) ? __expf(s4 - mx) : 0.f;

        float sum = ((e0 + e1) + (e2 + e3)) + e4;
        sum += __shfl_xor_sync(0xffffffffu, sum, 4);
        sum += __shfl_xor_sync(0xffffffffu, sum, 2);
        sum += __shfl_xor_sync(0xffffffffu, sum, 1);
        float inv = 1.f / sum;

        float p0 = e0 * inv, p1 = e1 * inv, p2 = e2 * inv, p3 = e3 * inv;
        srow[j]      = p0;
        srow[j + 8]  = p1;
        srow[j + 16] = p2;
        srow[j + 24] = p3;

        float* po = out_p + (size_t)(b * S_LEN + gq) * W_SZ;
        po[j]      = p0;
        po[j + 8]  = p1;
        po[j + 16] = p2;
        po[j + 24] = p3;
        if (j == 0) {
            float p4 = e4 * inv;
            srow[32] = p4;
            po[32]   = p4;
        }
    }
    __syncwarp();

    // ---- pass 2: lane owns 32B d-slice at 2*lane; packed f32x2 FMA ----
    ulonglong2 acc[QW][2];
    #pragma unroll
    for (int q = 0; q < QW; ++q) {
        acc[q][0].x = 0ull; acc[q][0].y = 0ull;
        acc[q][1].x = 0ull; acc[q][1].y = 0ull;
    }

    const ulonglong2* Vsm2 = reinterpret_cast<const ulonglong2*>(Vsm);
    const float* sbase = Ssm + lq0 * W_SZ;
    #pragma unroll 4
    for (int r = 0; r < NR; ++r) {
        int m = lq0 + r;
        const ulonglong2* vrow = Vsm2 + m * D4 + 2 * lane;
        ulonglong2 v0 = vrow[0];
        ulonglong2 v1 = vrow[1];
        #pragma unroll
        for (int q = 0; q < QW; ++q) {
            int wpos = r - q;
            float pv = (wpos >= 0 && wpos < W_SZ) ? sbase[q * W_SZ + wpos] : 0.f;
            ull p2 = pack2(pv);
            acc[q][0].x = fma2(p2, v0.x, acc[q][0].x);
            acc[q][0].y = fma2(p2, v0.y, acc[q][0].y);
            acc[q][1].x = fma2(p2, v1.x, acc[q][1].x);
            acc[q][1].y = fma2(p2, v1.y, acc[q][1].y);
        }
    }

    ulonglong2* obase = reinterpret_cast<ulonglong2*>(
        out_vals + ((size_t)b * S_LEN + base + lq0) * D_DIM);
    #pragma unroll
    for (int q = 0; q < QW; ++q) {
        obase[q * D4 + 2 * lane]     = acc[q][0];
        obase[q * D4 + 2 * lane + 1] = acc[q][1];
    }
}

extern "C" void kernel_launch(void* const* d_in, const int* in_sizes, int n_in,
                              void* d_out, int out_size)
{
    const float* q    = (const float*)d_in[0];
    const float* k    = (const float*)d_in[1];
    const float* v    = (const float*)d_in[2];
    const int*   mask = (const int*)d_in[3];

    float* out_vals = (float*)d_out;
    float* out_p    = out_vals + (size_t)B_SZ * S_LEN * D_DIM;

    static bool attr_set = false;
    if (!attr_set) {
        cudaFuncSetAttribute(local_attn_kernel,
                             cudaFuncAttributeMaxDynamicSharedMemorySize,
                             SMEM_BYTES);
        attr_set = true;
    }

    dim3 grid(S_LEN / TILE_Q, B_SZ);   // 128 CTAs, one wave
    local_attn_kernel<<<grid, THREADS, SMEM_BYTES>>>(q, k, v, mask, out_vals, out_p);
}

// round 5
// speedup vs baseline: 1.5913x; 1.0498x over previous
#include <cuda_runtime.h>
#include <cstddef>
#include <cstdint>

// LocalAttention: B=4, S=2048, D=256, W=33
// out = [values (B,S,D) | p_attn (B,S,W)] as float32

#define S_LEN   2048
#define D_DIM   256
#define B_SZ    4
#define W_SZ    33
#define HALF_W  16
#define TILE_Q  64
#define THREADS 512                // 16 warps
#define QW      4                  // queries per warp
#define ROWS    (TILE_Q + 2*HALF_W)  // 96 K/V rows in smem
#define D4      (D_DIM/4)          // 64 float4 per row
#define NR      (QW + 2*HALF_W)    // 36 rows per warp

#define SMEM_BYTES (ROWS*D_DIM*4*2 + TILE_Q*W_SZ*4 + ROWS*4)

typedef unsigned long long ull;

__device__ __forceinline__ ull fma2(ull a, ull b, ull c) {
    ull d;
    asm("fma.rn.f32x2 %0, %1, %2, %3;" : "=l"(d) : "l"(a), "l"(b), "l"(c));
    return d;
}
__device__ __forceinline__ float f32x2_sum(ull v) {
    float lo, hi;
    asm("mov.b64 {%0, %1}, %2;" : "=f"(lo), "=f"(hi) : "l"(v));
    return lo + hi;
}
__device__ __forceinline__ ull pack2(float x) {
    ull d;
    asm("mov.b64 %0, {%1, %1};" : "=l"(d) : "f"(x));
    return d;
}
__device__ __forceinline__ void cp16(void* smem_dst, const void* gsrc) {
    uint32_t s = (uint32_t)__cvta_generic_to_shared(smem_dst);
    asm volatile("cp.async.cg.shared.global [%0], [%1], 16;" :: "r"(s), "l"(gsrc));
}

__global__ void __launch_bounds__(THREADS, 1)
local_attn_kernel(const float* __restrict__ qg,
                  const float* __restrict__ kg,
                  const float* __restrict__ vg,
                  const int*   __restrict__ maskg,
                  float* __restrict__ out_vals,
                  float* __restrict__ out_p)
{
    extern __shared__ float smem[];
    float4* Ksm = reinterpret_cast<float4*>(smem);
    float4* Vsm = Ksm + ROWS * D4;
    float*  Ssm = reinterpret_cast<float*>(Vsm + ROWS * D4);   // [TILE_Q][W_SZ]
    int*    Fsm = reinterpret_cast<int*>(Ssm + TILE_Q * W_SZ); // [ROWS]

    const int tile = blockIdx.x;
    const int b    = blockIdx.y;
    const int base = tile * TILE_Q;
    const int r0   = base - HALF_W;
    const int tid  = threadIdx.x;

    const float4* kg4 = reinterpret_cast<const float4*>(kg + (size_t)b * S_LEN * D_DIM);
    const float4* vg4 = reinterpret_cast<const float4*>(vg + (size_t)b * S_LEN * D_DIM);

    // ---- async-stage K (group committed first) ----
    #pragma unroll
    for (int it = 0; it < ROWS * D4 / THREADS; ++it) {   // 12 iters
        int idx  = tid + it * THREADS;
        int row  = idx >> 6;
        int col  = idx & (D4 - 1);
        int grow = r0 + row;
        int gcl  = grow < 0 ? 0 : (grow >= S_LEN ? S_LEN - 1 : grow);
        cp16(Ksm + idx, kg4 + (size_t)gcl * D4 + col);
    }
    asm volatile("cp.async.commit_group;" ::: "memory");

    // ---- async-stage V (second group; waited only before pass 2) ----
    #pragma unroll
    for (int it = 0; it < ROWS * D4 / THREADS; ++it) {
        int idx  = tid + it * THREADS;
        int row  = idx >> 6;
        int col  = idx & (D4 - 1);
        int grow = r0 + row;
        int gcl  = grow < 0 ? 0 : (grow >= S_LEN ? S_LEN - 1 : grow);
        cp16(Vsm + idx, vg4 + (size_t)gcl * D4 + col);
    }
    asm volatile("cp.async.commit_group;" ::: "memory");

    // ---- mask flags (plain ld/st, small) ----
    if (tid < ROWS) {
        int grow = r0 + tid;
        int f = 0;
        if (grow >= 0 && grow < S_LEN) f = (maskg[b * S_LEN + grow] != 0);
        Fsm[tid] = f;
    }

    const int warp = tid >> 5;
    const int lane = tid & 31;
    const int lq0  = warp * QW;

    // pass-1 lane decomposition
    const int h  = lane >> 4;        // 0/1 : which row of the pair
    const int p  = lane & 15;        // 16-lane d-position
    const int g4 = (lane >> 2) & 3;  // query for final reduce
    const bool wlane = ((lane & 3) == 0);

    // ---- Q fragments (LDG overlaps the cp.async drain) ----
    ulonglong2 qf[QW][4];
    {
        const ulonglong2* qb = reinterpret_cast<const ulonglong2*>(
            qg + ((size_t)b * S_LEN + base + lq0) * D_DIM);
        #pragma unroll
        for (int q = 0; q < QW; ++q)
            #pragma unroll
            for (int c = 0; c < 4; ++c)
                qf[q][c] = qb[q * D4 + p + 16 * c];
    }

    // wait for K (V may still be in flight), then block-sync
    asm volatile("cp.async.wait_group 1;" ::: "memory");
    __syncthreads();

    const ulonglong2* Ksm2 = reinterpret_cast<const ulonglong2*>(Ksm);
    float* swarp = Ssm + lq0 * W_SZ;

    // ---- pass 1: scores, two rows per iteration ----
    #pragma unroll 2
    for (int ri = 0; ri < NR / 2; ++ri) {   // 18 iters
        int m = lq0 + 2 * ri + h;
        const ulonglong2* krow = Ksm2 + m * D4 + p;
        ulonglong2 k0 = krow[0];
        ulonglong2 k1 = krow[16];
        ulonglong2 k2 = krow[32];
        ulonglong2 k3 = krow[48];

        float s[QW];
        #pragma unroll
        for (int q = 0; q < QW; ++q) {
            ull a0 = fma2(k0.x, qf[q][0].x, 0ull);
            ull a1 = fma2(k0.y, qf[q][0].y, 0ull);
            a0 = fma2(k1.x, qf[q][1].x, a0);
            a1 = fma2(k1.y, qf[q][1].y, a1);
            a0 = fma2(k2.x, qf[q][2].x, a0);
            a1 = fma2(k2.y, qf[q][2].y, a1);
            a0 = fma2(k3.x, qf[q][3].x, a0);
            a1 = fma2(k3.y, qf[q][3].y, a1);
            s[q] = f32x2_sum(a0) + f32x2_sum(a1);
        }
        #pragma unroll
        for (int q = 0; q < QW; ++q) s[q] += __shfl_xor_sync(0xffffffffu, s[q], 8);
        #pragma unroll
        for (int q = 0; q < QW; ++q) s[q] += __shfl_xor_sync(0xffffffffu, s[q], 4);
        float v = (g4 == 0) ? s[0] : (g4 == 1) ? s[1] : (g4 == 2) ? s[2] : s[3];
        v += __shfl_xor_sync(0xffffffffu, v, 2);
        v += __shfl_xor_sync(0xffffffffu, v, 1);

        int rl = 2 * ri + h;
        int wpos = rl - g4;
        if (wlane && wpos >= 0 && wpos < W_SZ) {
            float sc = Fsm[m] ? v * 0.0625f : -1e10f;   // * 1/sqrt(256)
            swarp[g4 * W_SZ + wpos] = sc;
        }
    }
    __syncwarp();

    // ---- warp-local softmax: 8 lanes per query ----
    const int g8 = lane >> 3;
    const int j  = lane & 7;
    const int lq = lq0 + g8;
    const int gq = base + lq;
    float* srow = Ssm + lq * W_SZ;
    {
        float s0 = srow[j];
        float s1 = srow[j + 8];
        float s2 = srow[j + 16];
        float s3 = srow[j + 24];
        float s4 = (j == 0) ? srow[32] : -3e38f;

        float mx = fmaxf(fmaxf(fmaxf(s0, s1), fmaxf(s2, s3)), s4);
        mx = fmaxf(mx, __shfl_xor_sync(0xffffffffu, mx, 4));
        mx = fmaxf(mx, __shfl_xor_sync(0xffffffffu, mx, 2));
        mx = fmaxf(mx, __shfl_xor_sync(0xffffffffu, mx, 1));

        float e0 = __expf(s0 - mx);
        float e1 = __expf(s1 - mx);
        float e2 = __expf(s2 - mx);
        float e3 = __expf(s3 - mx);
        float e4 = (j == 0) ? __expf(s4 - mx) : 0.f;

        float sum = ((e0 + e1) + (e2 + e3)) + e4;
        sum += __shfl_xor_sync(0xffffffffu, sum, 4);
        sum += __shfl_xor_sync(0xffffffffu, sum, 2);
        sum += __shfl_xor_sync(0xffffffffu, sum, 1);
        float inv = 1.f / sum;

        float p0 = e0 * inv, p1 = e1 * inv, p2 = e2 * inv, p3 = e3 * inv;
        srow[j]      = p0;
        srow[j + 8]  = p1;
        srow[j + 16] = p2;
        srow[j + 24] = p3;

        float* po = out_p + (size_t)(b * S_LEN + gq) * W_SZ;
        po[j]      = p0;
        po[j + 8]  = p1;
        po[j + 16] = p2;
        po[j + 24] = p3;
        if (j == 0) {
            float p4 = e4 * inv;
            srow[32] = p4;
            po[32]   = p4;
        }
    }

    // V must be resident + visible block-wide before pass 2
    asm volatile("cp.async.wait_group 0;" ::: "memory");
    __syncthreads();

    // ---- pass 2: lane owns 32B d-slice at 2*lane; packed f32x2 FMA ----
    ulonglong2 acc[QW][2];
    #pragma unroll
    for (int q = 0; q < QW; ++q) {
        acc[q][0].x = 0ull; acc[q][0].y = 0ull;
        acc[q][1].x = 0ull; acc[q][1].y = 0ull;
    }

    const ulonglong2* Vsm2 = reinterpret_cast<const ulonglong2*>(Vsm);
    const float* sbase = Ssm + lq0 * W_SZ;
    #pragma unroll 4
    for (int r = 0; r < NR; ++r) {
        int m = lq0 + r;
        const ulonglong2* vrow = Vsm2 + m * D4 + 2 * lane;
        ulonglong2 v0 = vrow[0];
        ulonglong2 v1 = vrow[1];
        #pragma unroll
        for (int q = 0; q < QW; ++q) {
            int wpos = r - q;
            float pv = (wpos >= 0 && wpos < W_SZ) ? sbase[q * W_SZ + wpos] : 0.f;
            ull p2 = pack2(pv);
            acc[q][0].x = fma2(p2, v0.x, acc[q][0].x);
            acc[q][0].y = fma2(p2, v0.y, acc[q][0].y);
            acc[q][1].x = fma2(p2, v1.x, acc[q][1].x);
            acc[q][1].y = fma2(p2, v1.y, acc[q][1].y);
        }
    }

    ulonglong2* obase = reinterpret_cast<ulonglong2*>(
        out_vals + ((size_t)b * S_LEN + base + lq0) * D_DIM);
    #pragma unroll
    for (int q = 0; q < QW; ++q) {
        obase[q * D4 + 2 * lane]     = acc[q][0];
        obase[q * D4 + 2 * lane + 1] = acc[q][1];
    }
}

extern "C" void kernel_launch(void* const* d_in, const int* in_sizes, int n_in,
                              void* d_out, int out_size)
{
    const float* q    = (const float*)d_in[0];
    const float* k    = (const float*)d_in[1];
    const float* v    = (const float*)d_in[2];
    const int*   mask = (const int*)d_in[3];

    float* out_vals = (float*)d_out;
    float* out_p    = out_vals + (size_t)B_SZ * S_LEN * D_DIM;

    static bool attr_set = false;
    if (!attr_set) {
        cudaFuncSetAttribute(local_attn_kernel,
                             cudaFuncAttributeMaxDynamicSharedMemorySize,
                             SMEM_BYTES);
        attr_set = true;
    }

    dim3 grid(S_LEN / TILE_Q, B_SZ);   // 128 CTAs, one wave
    local_attn_kernel<<<grid, THREADS, SMEM_BYTES>>>(q, k, v, mask, out_vals, out_p);
}